// round 9
// baseline (speedup 1.0000x reference)
#include <cuda_runtime.h>

// NoQmix_74560632258885 — FINAL (held from R5/R8; identical source)
//
// Algebraic identity (verified across 7 passing runs, rel_err 1.68-1.71e-7):
// softmax(e, axis=1) is normalized over the same axis the final einsum
// ('bij,bj->b') sums over, so Σ_i attention[b,i,j] == 1 for every (b, j) —
// including fully-masked columns (uniform softmax still sums to 1). Hence
//   q_tot[b] = Σ_j agent_qs[b,j]
// independent of features, adj, states, W, a. The 34-GFLOP GAT pipeline in
// the reference is algebraically dead; the kernel is a 4096x64 fp32 row-sum.
//
// Measurement summary: R8 ran THIS EXACT SOURCE at 5.15us vs R5's 6.08us ->
// hold-to-hold noise is ~+-1us, swamping all config deltas. Robust findings:
//   - all >=64-block configs equivalent (~5-6.5us band)
//   - <64 blocks regresses (32blk: 6.82us, SM starvation)
//   - duration = fixed graph-replay/launch overhead + one DRAM-latency
//     exposure; 1MB of traffic is ~0.15us at spec BW.
// Config: 128 CTAs x 128 threads, 4 threads/row, 4 independent LDG.128 per
// thread (64B contiguous), 2-step shfl reduce. Session win was the algebra.

__global__ void __launch_bounds__(128)
rowsum64_final_kernel(const float4* __restrict__ qs4,
                      float* __restrict__ out,
                      int rows) {
    int t = blockIdx.x * blockDim.x + threadIdx.x;   // global thread id
    int row = t >> 2;                                 // 4 threads per row
    if (row >= rows) return;

    // Thread t owns float4 indices [4t, 4t+3] — 64B contiguous, 4 independent
    // LDG.128 in flight per thread.
    const float4* p = qs4 + 4 * t;
    float4 v0 = p[0];
    float4 v1 = p[1];
    float4 v2 = p[2];
    float4 v3 = p[3];

    float s = ((v0.x + v0.y) + (v0.z + v0.w))
            + ((v1.x + v1.y) + (v1.z + v1.w))
            + ((v2.x + v2.y) + (v2.z + v2.w))
            + ((v3.x + v3.y) + (v3.z + v3.w));

    // Reduce across the 4 lanes of this row (consecutive in-warp).
    s += __shfl_xor_sync(0xffffffffu, s, 2);
    s += __shfl_xor_sync(0xffffffffu, s, 1);

    if ((t & 3) == 0) out[row] = s;
}

extern "C" void kernel_launch(void* const* d_in, const int* in_sizes, int n_in,
                              void* d_out, int out_size) {
    // metadata order: features[0], agent_qs[1], adj[2], states[3], W[4], a[5]
    const float4* agent_qs4 = (const float4*)d_in[1];
    float* out = (float*)d_out;

    int rows = out_size;                 // B = 4096
    int total_threads = rows * 4;        // 4 threads per row
    int threads = 128;
    int blocks = (total_threads + threads - 1) / threads;   // 128

    rowsum64_final_kernel<<<blocks, threads>>>(agent_qs4, out, rows);
}

// round 10
// speedup vs baseline: 1.2075x; 1.2075x over previous
#include <cuda_runtime.h>

// NoQmix_74560632258885 — FINAL (held; identical to R5/R8/R9 source)
//
// Algebraic identity (verified across 8 passing runs, rel_err 1.68-1.71e-7):
// softmax(e, axis=1) is normalized over the same axis the final einsum
// ('bij,bj->b') sums over, so Σ_i attention[b,i,j] == 1 for every (b, j) —
// including fully-masked columns (uniform softmax still sums to 1). Hence
//   q_tot[b] = Σ_j agent_qs[b,j]
// independent of features, adj, states, W, a. The 34-GFLOP GAT pipeline in
// the reference is algebraically dead; the kernel is a 4096x64 fp32 row-sum.
//
// Measurement summary: THIS EXACT SOURCE measured 6.08 (R5), 5.15 (R8),
// 6.14 (R9) us -> hold-to-hold noise ~+-0.5-1us swamps every config delta.
// Robust findings only:
//   - all >=64-block layouts statistically equivalent (~5-6.5us band)
//   - <64 blocks genuinely regresses (32blk: 6.82us, SM starvation)
//   - duration = fixed graph-replay/launch overhead + one DRAM-latency
//     exposure; 1MB of traffic is ~0.15us at spec BW.
// No remaining change has expected effect above noise; holding the measured
// optimum. Config: 128 CTAs x 128 threads, 4 threads/row, 4 independent
// LDG.128 per thread (64B contiguous), 2-step shfl reduce.
// Session win was the algebra, not the SASS.

__global__ void __launch_bounds__(128)
rowsum64_final_kernel(const float4* __restrict__ qs4,
                      float* __restrict__ out,
                      int rows) {
    int t = blockIdx.x * blockDim.x + threadIdx.x;   // global thread id
    int row = t >> 2;                                 // 4 threads per row
    if (row >= rows) return;

    // Thread t owns float4 indices [4t, 4t+3] — 64B contiguous, 4 independent
    // LDG.128 in flight per thread.
    const float4* p = qs4 + 4 * t;
    float4 v0 = p[0];
    float4 v1 = p[1];
    float4 v2 = p[2];
    float4 v3 = p[3];

    float s = ((v0.x + v0.y) + (v0.z + v0.w))
            + ((v1.x + v1.y) + (v1.z + v1.w))
            + ((v2.x + v2.y) + (v2.z + v2.w))
            + ((v3.x + v3.y) + (v3.z + v3.w));

    // Reduce across the 4 lanes of this row (consecutive in-warp).
    s += __shfl_xor_sync(0xffffffffu, s, 2);
    s += __shfl_xor_sync(0xffffffffu, s, 1);

    if ((t & 3) == 0) out[row] = s;
}

extern "C" void kernel_launch(void* const* d_in, const int* in_sizes, int n_in,
                              void* d_out, int out_size) {
    // metadata order: features[0], agent_qs[1], adj[2], states[3], W[4], a[5]
    const float4* agent_qs4 = (const float4*)d_in[1];
    float* out = (float*)d_out;

    int rows = out_size;                 // B = 4096
    int total_threads = rows * 4;        // 4 threads per row
    int threads = 128;
    int blocks = (total_threads + threads - 1) / threads;   // 128

    rowsum64_final_kernel<<<blocks, threads>>>(agent_qs4, out, rows);
}